// round 1
// baseline (speedup 1.0000x reference)
#include <cuda_runtime.h>
#include <cstdint>

#define B_   4
#define C_   128
#define H_   96
#define W_   96
#define HW_  (H_*W_)        // 9216
#define P_   (B_*HW_)       // 36864
#define E_   8
#define NEX  9              // 8 experts + shared-as-expert-8
#define TILE_P 64
#define CHUNK_CI 4
#define CHUNK_K  (CHUNK_CI*9)  // 36

// ---------------- scratch (device globals; no allocation) ----------------
__device__ float g_wT[NEX*C_*9*C_];            // [ex][ci][tap][co]  (5.3 MB)
__device__ float g_bias[NEX*C_];               // [ex][co]
__device__ int   g_count[16];
__device__ unsigned long long g_list[NEX][P_]; // packed: (w_bits<<32)|(slot<<20)|pid
__device__ float g_partial[2*C_*P_];           // [slot][co][pid]    (37.7 MB)

// ---------------- init: counters + identity list for shared expert -------
__global__ void k_init() {
    int i = blockIdx.x * blockDim.x + threadIdx.x;
    if (i < 16) g_count[i] = (i == 8) ? P_ : 0;
    if (i < P_)
        g_list[8][i] = (((unsigned long long)__float_as_uint(1.0f)) << 32) | (unsigned)i;
}

// ---------------- weight repack: [ex][ci][tap][co] -----------------------
__global__ void k_transpose(const float* __restrict__ ew, const float* __restrict__ sw,
                            const float* __restrict__ eb, const float* __restrict__ sb) {
    int idx = blockIdx.x * blockDim.x + threadIdx.x;
    const int total = NEX*C_*9*C_;
    if (idx < total) {
        int co  = idx & 127;
        int tap = (idx >> 7) % 9;
        int ci  = (idx / (C_*9)) & 127;
        int ex  = idx / (C_*9*C_);
        float v;
        if (ex < 8) v = ew[((ex*C_ + co)*C_ + ci)*9 + tap];
        else        v = sw[(co*C_ + ci)*9 + tap];
        g_wT[idx] = v;
    }
    if (idx < NEX*C_) {
        int ex = idx >> 7, co = idx & 127;
        g_bias[idx] = (ex < 8) ? eb[idx] : sb[co];
    }
}

// ---------------- gate: conv(8ch) + sigmoid + top2 + softmax + route -----
__global__ void k_gate(const float* __restrict__ x, const float* __restrict__ gw,
                       const float* __restrict__ gbias) {
    __shared__ float sgw[E_*C_*9];   // 9216 floats = 36 KB
    for (int i = threadIdx.x; i < E_*C_*9; i += blockDim.x) sgw[i] = gw[i];
    __syncthreads();

    int pid = blockIdx.x * blockDim.x + threadIdx.x;
    if (pid >= P_) return;
    int b  = pid / HW_;
    int hw = pid - b*HW_;
    int h  = hw / W_, w = hw - h*W_;
    const float* xb = x + (size_t)b*C_*HW_ + hw;
    bool hm = h > 0, hp = h < H_-1, wm = w > 0, wp = w < W_-1;

    float acc[E_];
    #pragma unroll
    for (int e = 0; e < E_; e++) acc[e] = 0.f;

    for (int ci = 0; ci < C_; ci++) {
        const float* xp = xb + ci*HW_;
        float xv[9];
        xv[0] = (hm && wm) ? xp[-W_-1] : 0.f;
        xv[1] =  hm        ? xp[-W_]   : 0.f;
        xv[2] = (hm && wp) ? xp[-W_+1] : 0.f;
        xv[3] =  wm        ? xp[-1]    : 0.f;
        xv[4] =              xp[0];
        xv[5] =  wp        ? xp[1]     : 0.f;
        xv[6] = (hp && wm) ? xp[W_-1]  : 0.f;
        xv[7] =  hp        ? xp[W_]    : 0.f;
        xv[8] = (hp && wp) ? xp[W_+1]  : 0.f;
        #pragma unroll
        for (int e = 0; e < E_; e++) {
            const float* wp9 = &sgw[(e*C_ + ci)*9];
            float a = acc[e];
            #pragma unroll
            for (int t = 0; t < 9; t++) a = fmaf(xv[t], wp9[t], a);
            acc[e] = a;
        }
    }

    float s[E_], bsc[E_];
    #pragma unroll
    for (int e = 0; e < E_; e++) {
        s[e]   = 1.f / (1.f + expf(-acc[e]));
        bsc[e] = s[e] + gbias[e];
    }
    // top-2 of biased, lowest index wins ties (matches lax.top_k)
    int e0 = 0;
    #pragma unroll
    for (int e = 1; e < E_; e++) if (bsc[e] > bsc[e0]) e0 = e;
    int e1 = (e0 == 0) ? 1 : 0;
    #pragma unroll
    for (int e = 0; e < E_; e++) if (e != e0 && bsc[e] > bsc[e1]) e1 = e;

    // softmax over UNBIASED scores at (e0, e1)
    float m  = fmaxf(s[e0], s[e1]);
    float d0 = expf(s[e0] - m), d1 = expf(s[e1] - m);
    float inv = 1.f / (d0 + d1);
    float w0 = d0 * inv, w1 = d1 * inv;

    int p0 = atomicAdd(&g_count[e0], 1);
    g_list[e0][p0] = (((unsigned long long)__float_as_uint(w0)) << 32) | (unsigned)pid;
    int p1 = atomicAdd(&g_count[e1], 1);
    g_list[e1][p1] = (((unsigned long long)__float_as_uint(w1)) << 32) | (unsigned)(pid | (1u << 20));
}

// ---------------- routed expert conv (GEMM-style, fp32) ------------------
__global__ __launch_bounds__(256, 3)
void k_expert(const float* __restrict__ x, float* __restrict__ out) {
    __shared__ float Ws[CHUNK_K*C_];      // [k][co]   4608 floats
    __shared__ float Xs[CHUNK_K*TILE_P];  // [k][px]   2304 floats
    __shared__ int      s_off[TILE_P];
    __shared__ float    s_wt[TILE_P];
    __shared__ int      s_pid[TILE_P];
    __shared__ int      s_slot[TILE_P];
    __shared__ unsigned s_msk[TILE_P];

    const int e = blockIdx.y;
    const int n = g_count[e];
    const int base = blockIdx.x * TILE_P;
    if (base >= n) return;
    const int tid = threadIdx.x;

    if (tid < TILE_P) {
        int idx = base + tid;
        float wt = 0.f; int pid = 0; int slot = 0;
        if (idx < n) {
            unsigned long long v = g_list[e][idx];
            wt   = __uint_as_float((unsigned)(v >> 32));
            unsigned lo = (unsigned)v;
            pid  = lo & 0xFFFFF;
            slot = (lo >> 20) & 1;
        }
        int b  = pid / HW_;
        int hw = pid - b*HW_;
        int h  = hw / W_, w = hw - h*W_;
        s_off[tid]  = b*C_*HW_ + hw;
        s_wt[tid]   = wt;
        s_pid[tid]  = pid;
        s_slot[tid] = slot;
        unsigned msk = 0;
        #pragma unroll
        for (int t = 0; t < 9; t++) {
            int dh = t/3 - 1, dw = t%3 - 1;
            int hh = h + dh, ww = w + dw;
            if (hh >= 0 && hh < H_ && ww >= 0 && ww < W_) msk |= 1u << t;
        }
        s_msk[tid] = msk;
    }
    __syncthreads();

    const int tx = tid & 15;   // pixel group: pixels tx*4 .. tx*4+3
    const int ty = tid >> 4;   // cout group:  couts  ty*8 .. ty*8+7
    float acc[4][8];
    #pragma unroll
    for (int p = 0; p < 4; p++)
        #pragma unroll
        for (int c = 0; c < 8; c++) acc[p][c] = 0.f;

    const float* wbase = g_wT + (size_t)e * (C_*9*C_);

    for (int ci0 = 0; ci0 < C_; ci0 += CHUNK_CI) {
        // weights: contiguous 4608 floats -> coalesced float4 copy
        {
            const float4* src = (const float4*)(wbase + ci0 * (9*C_));
            float4* dst = (float4*)Ws;
            #pragma unroll
            for (int i = tid; i < CHUNK_K*C_/4; i += 256) dst[i] = src[i];
        }
        // gathered x tile with zero padding
        for (int idx = tid; idx < CHUNK_K*TILE_P; idx += 256) {
            int k = idx >> 6;
            int i = idx & 63;
            int cc = k / 9, t = k - cc*9;
            int dh = t/3 - 1, dw = t - (t/3)*3 - 1;
            float v = 0.f;
            if ((s_msk[i] >> t) & 1)
                v = x[s_off[i] + (ci0 + cc)*HW_ + dh*W_ + dw];
            Xs[idx] = v;
        }
        __syncthreads();

        #pragma unroll 6
        for (int k = 0; k < CHUNK_K; k++) {
            float4 xv = *(const float4*)&Xs[k*TILE_P + tx*4];
            float4 wa = *(const float4*)&Ws[k*C_ + ty*8];
            float4 wb = *(const float4*)&Ws[k*C_ + ty*8 + 4];
            float xs[4] = {xv.x, xv.y, xv.z, xv.w};
            float wc[8] = {wa.x, wa.y, wa.z, wa.w, wb.x, wb.y, wb.z, wb.w};
            #pragma unroll
            for (int p = 0; p < 4; p++)
                #pragma unroll
                for (int c = 0; c < 8; c++)
                    acc[p][c] = fmaf(xs[p], wc[c], acc[p][c]);
        }
        __syncthreads();
    }

    const bool e8 = (e == 8);
    #pragma unroll
    for (int p = 0; p < 4; p++) {
        int i = tx*4 + p;
        float wt = s_wt[i];
        if (wt == 0.f) continue;
        int off = s_off[i];
        int pid = s_pid[i];
        int sl  = s_slot[i];
        #pragma unroll
        for (int c = 0; c < 8; c++) {
            int co = ty*8 + c;
            float v = acc[p][c] + g_bias[e*C_ + co];
            if (e8) out[off + co*HW_] = v;                       // shared: direct write
            else    g_partial[(sl*C_ + co)*P_ + pid] = wt * v;   // routed: once per (slot,pixel)
        }
    }
}

// ---------------- combine: out += partial0 + partial1 --------------------
__global__ void k_combine(float* __restrict__ out) {
    int idx = blockIdx.x * blockDim.x + threadIdx.x;
    int i = idx * 4;
    if (i >= B_*C_*HW_) return;
    int bco = i / HW_;
    int hw  = i - bco*HW_;
    int b   = bco >> 7;
    int co  = bco & 127;
    int pid = b*HW_ + hw;
    float4 o  = *(float4*)&out[i];
    float4 p0 = *(const float4*)&g_partial[(0*C_ + co)*P_ + pid];
    float4 p1 = *(const float4*)&g_partial[(1*C_ + co)*P_ + pid];
    o.x += p0.x + p1.x;
    o.y += p0.y + p1.y;
    o.z += p0.z + p1.z;
    o.w += p0.w + p1.w;
    *(float4*)&out[i] = o;
}

// ---------------- launch --------------------------------------------------
extern "C" void kernel_launch(void* const* d_in, const int* in_sizes, int n_in,
                              void* d_out, int out_size) {
    const float* x  = (const float*)d_in[0];
    const float* gw = (const float*)d_in[1];
    const float* gb = (const float*)d_in[2];
    const float* ew = (const float*)d_in[3];
    const float* eb = (const float*)d_in[4];
    const float* sw = (const float*)d_in[5];
    const float* sb = (const float*)d_in[6];
    float* out = (float*)d_out;

    k_init<<<(P_ + 255)/256, 256>>>();
    k_transpose<<<(NEX*C_*9*C_ + 255)/256, 256>>>(ew, sw, eb, sb);
    k_gate<<<(P_ + 255)/256, 256>>>(x, gw, gb);
    dim3 grid_e(P_/TILE_P, NEX);   // 576 tiles x 9 experts, empty tiles early-exit
    k_expert<<<grid_e, 256>>>(x, out);
    k_combine<<<(B_*C_*HW_/4 + 255)/256, 256>>>(out);
}

// round 3
// speedup vs baseline: 2.1583x; 2.1583x over previous
#include <cuda_runtime.h>
#include <cuda_bf16.h>
#include <cstdint>

#define B_    4
#define C_    128
#define H_    96
#define W_    96
#define HW_   (H_*W_)          // 9216
#define P_    (B_*HW_)         // 36864
#define E_    8
#define NEX   9
#define WP_   98
#define HP_   98
#define HWP_  (HP_*WP_)        // 9604
#define PPAD_ (B_*HWP_)        // 38416
#define NCHUNK 36              // K=1152 in chunks of 32

// ---------------- device globals (no allocation) --------------------------
__device__ uint32_t g_xT[PPAD_*C_];            // packed (bf16 hi | lo<<16), NHWC padded (19.7MB)
__device__ uint32_t g_wBf[NEX*NCHUNK*4096];    // B frags: [e][chunk][hi 2048 | lo 2048] (5.3MB)
__device__ float    g_bias[NEX*C_];
__device__ int      g_count[E_];
__device__ unsigned long long g_list[E_][P_];  // (w_bits<<32)|(slot<<20)|pid
__device__ float    g_partial[3*P_*C_];        // [slot][pid][co]  (56.6MB)

// ---------------- helpers --------------------------------------------------
__device__ __forceinline__ uint32_t pack_split(float v) {
    __nv_bfloat16 h = __float2bfloat16(v);
    float r = v - __bfloat162float(h);
    __nv_bfloat16 l = __float2bfloat16(r);
    return (uint32_t)__bfloat16_as_ushort(h) | ((uint32_t)__bfloat16_as_ushort(l) << 16);
}

__device__ __forceinline__ void mma_bf16(float* c, const uint32_t* a, const uint32_t* b) {
    asm volatile(
        "mma.sync.aligned.m16n8k16.row.col.f32.bf16.bf16.f32 "
        "{%0,%1,%2,%3}, {%4,%5,%6,%7}, {%8,%9}, {%0,%1,%2,%3};"
        : "+f"(c[0]), "+f"(c[1]), "+f"(c[2]), "+f"(c[3])
        : "r"(a[0]), "r"(a[1]), "r"(a[2]), "r"(a[3]), "r"(b[0]), "r"(b[1]));
}

// ---------------- prep kernels ---------------------------------------------
__global__ void k_init() {
    int i = blockIdx.x * blockDim.x + threadIdx.x;
    if (i < E_) g_count[i] = 0;
}

__global__ void k_zero_xpad() {
    int i = blockIdx.x * blockDim.x + threadIdx.x;
    if (i < PPAD_*C_/4) ((uint4*)g_xT)[i] = make_uint4(0u, 0u, 0u, 0u);
}

__global__ void k_nhwc(const float* __restrict__ x) {
    __shared__ float t[32][33];
    int hw0 = blockIdx.x * 32, ci0 = blockIdx.y * 32, b = blockIdx.z;
    int tid = threadIdx.x;
    #pragma unroll
    for (int r = 0; r < 4; r++) {
        int ci = (tid >> 5) + r*8, hw = tid & 31;
        t[ci][hw] = x[((b*C_) + ci0 + ci)*HW_ + hw0 + hw];
    }
    __syncthreads();
    #pragma unroll
    for (int r = 0; r < 4; r++) {
        int hwl = (tid >> 5) + r*8, cil = tid & 31;
        int hw = hw0 + hwl, h = hw / W_, w = hw - h*W_;
        int pad = b*HWP_ + (h+1)*WP_ + (w+1);
        g_xT[(size_t)pad*C_ + ci0 + cil] = pack_split(t[cil][hwl]);
    }
}

// weights -> mma fragment order, split into bf16 hi/lo, packed per ci pair
__global__ void k_repackB(const float* __restrict__ ew, const float* __restrict__ sw,
                          const float* __restrict__ eb, const float* __restrict__ sb) {
    int idx = blockIdx.x * blockDim.x + threadIdx.x;
    // idx over e(9) * co(128) * tap(9) * cipair(64)
    const int total = NEX*C_*9*64;
    if (idx < total) {
        int cip = idx & 63;
        int tap = (idx >> 6) % 9;
        int co  = (idx / (64*9)) & 127;
        int e   = idx / (64*9*C_);
        int ci  = cip * 2;
        float v0, v1;
        if (e < 8) {
            int base = ((e*C_ + co)*C_ + ci)*9 + tap;
            v0 = ew[base]; v1 = ew[base + 9];
        } else {
            int base = (co*C_ + ci)*9 + tap;
            v0 = sw[base]; v1 = sw[base + 9];
        }
        uint32_t p0 = pack_split(v0), p1 = pack_split(v1);
        // p: hi in low16, lo in high16
        uint32_t hi = (p0 & 0xFFFFu) | (p1 << 16);
        uint32_t lo = (p0 >> 16) | (p1 & 0xFFFF0000u);
        int k_abs = tap*C_ + ci;
        int chunk = k_abs >> 5;
        int k0 = k_abs & 31;
        int ks = k0 >> 4;
        int lane = ((co & 7) << 2) + ((k0 & 7) >> 1);
        int reg  = (k0 >> 3) & 1;
        int nt   = co >> 3;
        size_t di = (size_t)(e*NCHUNK + chunk)*4096 + ((ks*16 + nt)*32 + lane)*2 + reg;
        g_wBf[di] = hi;
        g_wBf[di + 2048] = lo;
    }
    if (idx < NEX*C_) {
        int ex = idx >> 7, co = idx & 127;
        g_bias[idx] = (ex < 8) ? eb[idx] : sb[co];
    }
}

// ---------------- gate: conv(8) + sigmoid + top2 + softmax + route --------
__global__ void k_gate(const float* __restrict__ x, const float* __restrict__ gw,
                       const float* __restrict__ gbias) {
    __shared__ float sgw[E_*C_*9];
    for (int i = threadIdx.x; i < E_*C_*9; i += blockDim.x) sgw[i] = gw[i];
    __syncthreads();

    int pid = blockIdx.x * blockDim.x + threadIdx.x;
    if (pid >= P_) return;
    int b = pid / HW_, hw = pid - b*HW_;
    int h = hw / W_, w = hw - h*W_;
    const float* xb = x + (size_t)b*C_*HW_ + hw;
    bool hm = h > 0, hp = h < H_-1, wm = w > 0, wp = w < W_-1;

    float acc[E_];
    #pragma unroll
    for (int e = 0; e < E_; e++) acc[e] = 0.f;
    for (int ci = 0; ci < C_; ci++) {
        const float* xp = xb + ci*HW_;
        float xv[9];
        xv[0] = (hm && wm) ? xp[-W_-1] : 0.f;
        xv[1] =  hm        ? xp[-W_]   : 0.f;
        xv[2] = (hm && wp) ? xp[-W_+1] : 0.f;
        xv[3] =  wm        ? xp[-1]    : 0.f;
        xv[4] =              xp[0];
        xv[5] =  wp        ? xp[1]     : 0.f;
        xv[6] = (hp && wm) ? xp[W_-1]  : 0.f;
        xv[7] =  hp        ? xp[W_]    : 0.f;
        xv[8] = (hp && wp) ? xp[W_+1]  : 0.f;
        #pragma unroll
        for (int e = 0; e < E_; e++) {
            const float* wp9 = &sgw[(e*C_ + ci)*9];
            float a = acc[e];
            #pragma unroll
            for (int t = 0; t < 9; t++) a = fmaf(xv[t], wp9[t], a);
            acc[e] = a;
        }
    }
    float s[E_], bsc[E_];
    #pragma unroll
    for (int e = 0; e < E_; e++) {
        s[e]   = 1.f / (1.f + expf(-acc[e]));
        bsc[e] = s[e] + gbias[e];
    }
    int e0 = 0;
    #pragma unroll
    for (int e = 1; e < E_; e++) if (bsc[e] > bsc[e0]) e0 = e;
    int e1 = (e0 == 0) ? 1 : 0;
    #pragma unroll
    for (int e = 0; e < E_; e++) if (e != e0 && bsc[e] > bsc[e1]) e1 = e;
    float m = fmaxf(s[e0], s[e1]);
    float d0 = expf(s[e0]-m), d1 = expf(s[e1]-m);
    float inv = 1.f / (d0 + d1);
    int p0 = atomicAdd(&g_count[e0], 1);
    g_list[e0][p0] = (((unsigned long long)__float_as_uint(d0*inv)) << 32) | (unsigned)pid;
    int p1 = atomicAdd(&g_count[e1], 1);
    g_list[e1][p1] = (((unsigned long long)__float_as_uint(d1*inv)) << 32) | (unsigned)(pid | (1u<<20));
}

// ---------------- bf16 mma.sync expert GEMM -------------------------------
// CTA: 128 pixels x 128 couts, one expert. 8 warps in 2(M)x4(N).
// Warp tile 64x32; 3-pass split bf16 (Ah*Bh + Ah*Bl + Al*Bh).
__global__ __launch_bounds__(256, 2)
void k_mma() {
    const int e    = blockIdx.y;
    const int tile = blockIdx.x;
    const int n    = (e < 8) ? g_count[e] : P_;
    if (tile * 128 >= n) return;

    __shared__ uint32_t sA[4096];    // [hi 2048 | lo 2048]: (ks*8+mt)*128 + lane*4 + reg
    __shared__ uint32_t sB[4096];    // [hi 2048 | lo 2048]: (ks*16+nt)*64 + lane*2 + reg
    __shared__ int   s_pid[128];
    __shared__ int   s_pp[128];
    __shared__ float s_wt[128];
    __shared__ float s_bias[128];

    const int tid = threadIdx.x;
    if (tid < 128) {
        int idx = tile*128 + tid;
        int pid = 0, slot = 0; float wt = 0.f;
        if (e < 8) {
            if (idx < n) {
                unsigned long long v = g_list[e][idx];
                wt   = __uint_as_float((unsigned)(v >> 32));
                unsigned lo = (unsigned)v;
                pid  = lo & 0xFFFFF;
                slot = (lo >> 20) & 1;
            }
        } else { pid = idx; wt = 1.f; slot = 2; }
        int b = pid / HW_, hw = pid - b*HW_;
        int h = hw / W_, w = hw - h*W_;
        s_pp[tid]   = (wt != 0.f) ? (b*HWP_ + (h+1)*WP_ + (w+1)) : (WP_ + 1);
        s_pid[tid]  = pid | (slot << 20);
        s_wt[tid]   = wt;
        s_bias[tid] = g_bias[e*C_ + tid];
    }
    __syncthreads();

    const int lane = tid & 31, wid = tid >> 5;
    const int wm = wid >> 2, wn = wid & 3;

    float c[4][4][4];
    #pragma unroll
    for (int i = 0; i < 4; i++)
        #pragma unroll
        for (int j = 0; j < 4; j++)
            #pragma unroll
            for (int k = 0; k < 4; k++) c[i][j][k] = 0.f;

    const int m_row = tid >> 3;      // A gather: 8 threads per pixel row
    const int kq    = tid & 7;

    uint4 pf[4];
    {   // prefetch A chunk 0
        const int t = 0, ci0 = 0;
        const int off = (t/3 - 1)*WP_ + (t%3 - 1);
        #pragma unroll
        for (int j = 0; j < 4; j++) {
            int m = m_row + j*32;
            pf[j] = *(const uint4*)(g_xT + (size_t)(s_pp[m] + off)*C_ + ci0 + kq*4);
        }
    }

    for (int ch = 0; ch < NCHUNK; ch++) {
        // ---- STS A fragments from prefetched regs ----
        {
            const int k0 = kq * 4;
            const int ks = k0 >> 4;
            const int la = ((k0 & 7) >> 1);            // + (m&7)*4 below
            const int rg_k = ((k0 >> 3) & 1) << 1;
            #pragma unroll
            for (int j = 0; j < 4; j++) {
                int m = m_row + j*32;
                int mt = m >> 4;
                int lane_a = ((m & 7) << 2) + la;
                int rg = ((m >> 3) & 1) + rg_k;
                int bi = ((ks*8 + mt)*32 + lane_a)*4 + rg;
                uint4 v = pf[j];
                sA[bi]          = __byte_perm(v.x, v.y, 0x5410);
                sA[bi + 2048]   = __byte_perm(v.x, v.y, 0x7632);
                sA[bi + 4]      = __byte_perm(v.z, v.w, 0x5410);
                sA[bi + 4+2048] = __byte_perm(v.z, v.w, 0x7632);
            }
        }
        // ---- copy B fragments (precomputed frag-order) ----
        {
            const uint4* bs = (const uint4*)(g_wBf + (size_t)(e*NCHUNK + ch)*4096);
            #pragma unroll
            for (int j = 0; j < 4; j++) ((uint4*)sB)[tid + j*256] = bs[tid + j*256];
        }
        __syncthreads();

        // prefetch next A chunk while mma runs
        if (ch + 1 < NCHUNK) {
            const int t = (ch+1) >> 2, ci0 = ((ch+1) & 3) * 32;
            const int off = (t/3 - 1)*WP_ + (t%3 - 1);
            #pragma unroll
            for (int j = 0; j < 4; j++) {
                int m = m_row + j*32;
                pf[j] = *(const uint4*)(g_xT + (size_t)(s_pp[m] + off)*C_ + ci0 + kq*4);
            }
        }

        #pragma unroll
        for (int ks = 0; ks < 2; ks++) {
            uint32_t bh[4][2], bl[4][2];
            #pragma unroll
            for (int nt = 0; nt < 4; nt++) {
                int ng = wn*4 + nt;
                uint2 h2 = ((const uint2*)(sB + (ks*16 + ng)*64))[lane];
                uint2 l2 = ((const uint2*)(sB + 2048 + (ks*16 + ng)*64))[lane];
                bh[nt][0] = h2.x; bh[nt][1] = h2.y;
                bl[nt][0] = l2.x; bl[nt][1] = l2.y;
            }
            #pragma unroll
            for (int mt = 0; mt < 4; mt++) {
                int mg = wm*4 + mt;
                uint4 ah4 = ((const uint4*)(sA + (ks*8 + mg)*128))[lane];
                uint4 al4 = ((const uint4*)(sA + 2048 + (ks*8 + mg)*128))[lane];
                uint32_t ah[4] = {ah4.x, ah4.y, ah4.z, ah4.w};
                uint32_t al[4] = {al4.x, al4.y, al4.z, al4.w};
                #pragma unroll
                for (int nt = 0; nt < 4; nt++) {
                    mma_bf16(c[mt][nt], ah, bh[nt]);
                    mma_bf16(c[mt][nt], ah, bl[nt]);
                    mma_bf16(c[mt][nt], al, bh[nt]);
                }
            }
        }
        __syncthreads();
    }

    // ---- epilogue: (acc + bias) * wt  ->  g_partial[slot][pid][co] ----
    #pragma unroll
    for (int mt = 0; mt < 4; mt++) {
        int r0 = wm*64 + mt*16 + (lane >> 2);
        #pragma unroll
        for (int half = 0; half < 2; half++) {
            int r = r0 + half*8;
            float wt = s_wt[r];
            if (wt != 0.f) {
                int pm  = s_pid[r];
                int pid = pm & 0xFFFFF;
                int slot = pm >> 20;
                float* dst = g_partial + ((size_t)slot*P_ + pid)*C_;
                #pragma unroll
                for (int nt = 0; nt < 4; nt++) {
                    int n0 = (wn*4 + nt)*8 + (lane & 3)*2;
                    float2 v;
                    v.x = (c[mt][nt][half*2 + 0] + s_bias[n0])     * wt;
                    v.y = (c[mt][nt][half*2 + 1] + s_bias[n0 + 1]) * wt;
                    *(float2*)(dst + n0) = v;
                }
            }
        }
    }
}

// ---------------- combine: out = p0 + p1 + p2 (transpose to NCHW) ---------
__global__ void k_combine(float* __restrict__ out) {
    __shared__ float t[32][33];
    int pid0 = blockIdx.x * 32, co0 = blockIdx.y * 32;
    int tid = threadIdx.x;
    #pragma unroll
    for (int r = 0; r < 4; r++) {
        int i = r*256 + tid;
        int pr = i >> 5, cl = i & 31;
        size_t o0 = ((size_t)(pid0 + pr))*C_ + co0 + cl;
        t[cl][pr] = g_partial[o0] + g_partial[(size_t)P_*C_ + o0]
                  + g_partial[2*(size_t)P_*C_ + o0];
    }
    __syncthreads();
    #pragma unroll
    for (int r = 0; r < 4; r++) {
        int i = r*256 + tid;
        int cl = i >> 5, pl = i & 31;
        int pid = pid0 + pl;
        int b = pid / HW_, hw = pid - b*HW_;
        out[((size_t)b*C_ + co0 + cl)*HW_ + hw] = t[cl][pl];
    }
}

// ---------------- launch ---------------------------------------------------
extern "C" void kernel_launch(void* const* d_in, const int* in_sizes, int n_in,
                              void* d_out, int out_size) {
    const float* x  = (const float*)d_in[0];
    const float* gw = (const float*)d_in[1];
    const float* gb = (const float*)d_in[2];
    const float* ew = (const float*)d_in[3];
    const float* eb = (const float*)d_in[4];
    const float* sw = (const float*)d_in[5];
    const float* sb = (const float*)d_in[6];
    float* out = (float*)d_out;

    k_init<<<1, 32>>>();
    k_zero_xpad<<<(PPAD_*C_/4 + 255)/256, 256>>>();
    k_nhwc<<<dim3(HW_/32, C_/32, B_), 256>>>(x);
    k_repackB<<<(NEX*C_*9*64 + 255)/256, 256>>>(ew, sw, eb, sb);
    k_gate<<<(P_ + 255)/256, 256>>>(x, gw, gb);
    k_mma<<<dim3(P_/128, NEX), 256>>>();
    k_combine<<<dim3(P_/32, C_/32), 256>>>(out);
}

// round 4
// speedup vs baseline: 2.5134x; 1.1645x over previous
#include <cuda_runtime.h>
#include <cuda_bf16.h>
#include <cstdint>

#define B_    4
#define C_    128
#define H_    96
#define W_    96
#define HW_   (H_*W_)          // 9216
#define P_    (B_*HW_)         // 36864
#define E_    8
#define NEX   9
#define WP_   98
#define HP_   98
#define HWP_  (HP_*WP_)        // 9604
#define PPAD_ (B_*HWP_)        // 38416
#define NCHUNK 36              // K=1152 in chunks of 32

// ---------------- device globals (no allocation) --------------------------
__device__ uint32_t g_xT[PPAD_*C_];            // packed (bf16 hi | lo<<16), NHWC padded (19.7MB)
__device__ uint32_t g_wBf[NEX*NCHUNK*4096];    // B frags: [e][chunk][hi 2048 | lo 2048] (5.3MB)
__device__ float    g_bias[NEX*C_];
__device__ int      g_count[E_];
__device__ unsigned long long g_list[E_][P_];  // (w_bits<<32)|(slot<<20)|pid
__device__ float    g_partial[3*P_*C_];        // [slot][pid][co]  (56.6MB)

// ---------------- helpers --------------------------------------------------
__device__ __forceinline__ uint32_t pack_split(float v) {
    __nv_bfloat16 h = __float2bfloat16(v);
    float r = v - __bfloat162float(h);
    __nv_bfloat16 l = __float2bfloat16(r);
    return (uint32_t)__bfloat16_as_ushort(h) | ((uint32_t)__bfloat16_as_ushort(l) << 16);
}

__device__ __forceinline__ void mma_bf16(float* c, const uint32_t* a, const uint32_t* b) {
    asm volatile(
        "mma.sync.aligned.m16n8k16.row.col.f32.bf16.bf16.f32 "
        "{%0,%1,%2,%3}, {%4,%5,%6,%7}, {%8,%9}, {%0,%1,%2,%3};"
        : "+f"(c[0]), "+f"(c[1]), "+f"(c[2]), "+f"(c[3])
        : "r"(a[0]), "r"(a[1]), "r"(a[2]), "r"(a[3]), "r"(b[0]), "r"(b[1]));
}

__device__ __forceinline__ uint32_t smem_u32(const void* p) {
    uint32_t a;
    asm("{ .reg .u64 t; cvta.to.shared.u64 t, %1; cvt.u32.u64 %0, t; }" : "=r"(a) : "l"(p));
    return a;
}
__device__ __forceinline__ void cp_async16(uint32_t dst, const void* src) {
    asm volatile("cp.async.cg.shared.global [%0], [%1], 16;" :: "r"(dst), "l"(src) : "memory");
}
#define CP_COMMIT() asm volatile("cp.async.commit_group;" ::: "memory")
#define CP_WAIT0()  asm volatile("cp.async.wait_group 0;" ::: "memory")

// ---------------- prep kernels ---------------------------------------------
__global__ void k_init() {
    int i = blockIdx.x * blockDim.x + threadIdx.x;
    if (i < E_) g_count[i] = 0;
}

__global__ void k_zero_xpad() {
    int i = blockIdx.x * blockDim.x + threadIdx.x;
    if (i < PPAD_*C_/4) ((uint4*)g_xT)[i] = make_uint4(0u, 0u, 0u, 0u);
}

__global__ void k_nhwc(const float* __restrict__ x) {
    __shared__ float t[32][33];
    int hw0 = blockIdx.x * 32, ci0 = blockIdx.y * 32, b = blockIdx.z;
    int tid = threadIdx.x;
    #pragma unroll
    for (int r = 0; r < 4; r++) {
        int ci = (tid >> 5) + r*8, hw = tid & 31;
        t[ci][hw] = x[((b*C_) + ci0 + ci)*HW_ + hw0 + hw];
    }
    __syncthreads();
    #pragma unroll
    for (int r = 0; r < 4; r++) {
        int hwl = (tid >> 5) + r*8, cil = tid & 31;
        int hw = hw0 + hwl, h = hw / W_, w = hw - h*W_;
        int pad = b*HWP_ + (h+1)*WP_ + (w+1);
        g_xT[(size_t)pad*C_ + ci0 + cil] = pack_split(t[cil][hwl]);
    }
}

// weights -> mma fragment order, split into bf16 hi/lo, packed per ci pair
__global__ void k_repackB(const float* __restrict__ ew, const float* __restrict__ sw,
                          const float* __restrict__ eb, const float* __restrict__ sb) {
    int idx = blockIdx.x * blockDim.x + threadIdx.x;
    const int total = NEX*C_*9*64;
    if (idx < total) {
        int cip = idx & 63;
        int tap = (idx >> 6) % 9;
        int co  = (idx / (64*9)) & 127;
        int e   = idx / (64*9*C_);
        int ci  = cip * 2;
        float v0, v1;
        if (e < 8) {
            int base = ((e*C_ + co)*C_ + ci)*9 + tap;
            v0 = ew[base]; v1 = ew[base + 9];
        } else {
            int base = (co*C_ + ci)*9 + tap;
            v0 = sw[base]; v1 = sw[base + 9];
        }
        uint32_t p0 = pack_split(v0), p1 = pack_split(v1);
        uint32_t hi = (p0 & 0xFFFFu) | (p1 << 16);
        uint32_t lo = (p0 >> 16) | (p1 & 0xFFFF0000u);
        int k_abs = tap*C_ + ci;
        int chunk = k_abs >> 5;
        int k0 = k_abs & 31;
        int ks = k0 >> 4;
        int lane = ((co & 7) << 2) + ((k0 & 7) >> 1);
        int reg  = (k0 >> 3) & 1;
        int nt   = co >> 3;
        size_t di = (size_t)(e*NCHUNK + chunk)*4096 + ((ks*16 + nt)*32 + lane)*2 + reg;
        g_wBf[di] = hi;
        g_wBf[di + 2048] = lo;
    }
    if (idx < NEX*C_) {
        int ex = idx >> 7, co = idx & 127;
        g_bias[idx] = (ex < 8) ? eb[idx] : sb[co];
    }
}

// ---------------- gate: conv(8) + sigmoid + top2 + softmax + route --------
__global__ void k_gate(const float* __restrict__ x, const float* __restrict__ gw,
                       const float* __restrict__ gbias) {
    __shared__ float sgw[E_*C_*9];
    for (int i = threadIdx.x; i < E_*C_*9; i += blockDim.x) sgw[i] = gw[i];
    __syncthreads();

    int pid = blockIdx.x * blockDim.x + threadIdx.x;
    if (pid >= P_) return;
    int b = pid / HW_, hw = pid - b*HW_;
    int h = hw / W_, w = hw - h*W_;
    const float* xb = x + (size_t)b*C_*HW_ + hw;
    bool hm = h > 0, hp = h < H_-1, wm = w > 0, wp = w < W_-1;

    float acc[E_];
    #pragma unroll
    for (int e = 0; e < E_; e++) acc[e] = 0.f;
    for (int ci = 0; ci < C_; ci++) {
        const float* xp = xb + ci*HW_;
        float xv[9];
        xv[0] = (hm && wm) ? xp[-W_-1] : 0.f;
        xv[1] =  hm        ? xp[-W_]   : 0.f;
        xv[2] = (hm && wp) ? xp[-W_+1] : 0.f;
        xv[3] =  wm        ? xp[-1]    : 0.f;
        xv[4] =              xp[0];
        xv[5] =  wp        ? xp[1]     : 0.f;
        xv[6] = (hp && wm) ? xp[W_-1]  : 0.f;
        xv[7] =  hp        ? xp[W_]    : 0.f;
        xv[8] = (hp && wp) ? xp[W_+1]  : 0.f;
        #pragma unroll
        for (int e = 0; e < E_; e++) {
            const float* wp9 = &sgw[(e*C_ + ci)*9];
            float a = acc[e];
            #pragma unroll
            for (int t = 0; t < 9; t++) a = fmaf(xv[t], wp9[t], a);
            acc[e] = a;
        }
    }
    float s[E_], bsc[E_];
    #pragma unroll
    for (int e = 0; e < E_; e++) {
        s[e]   = 1.f / (1.f + expf(-acc[e]));
        bsc[e] = s[e] + gbias[e];
    }
    int e0 = 0;
    #pragma unroll
    for (int e = 1; e < E_; e++) if (bsc[e] > bsc[e0]) e0 = e;
    int e1 = (e0 == 0) ? 1 : 0;
    #pragma unroll
    for (int e = 0; e < E_; e++) if (e != e0 && bsc[e] > bsc[e1]) e1 = e;
    float m = fmaxf(s[e0], s[e1]);
    float d0 = expf(s[e0]-m), d1 = expf(s[e1]-m);
    float inv = 1.f / (d0 + d1);
    int p0 = atomicAdd(&g_count[e0], 1);
    g_list[e0][p0] = (((unsigned long long)__float_as_uint(d0*inv)) << 32) | (unsigned)pid;
    int p1 = atomicAdd(&g_count[e1], 1);
    g_list[e1][p1] = (((unsigned long long)__float_as_uint(d1*inv)) << 32) | (unsigned)(pid | (1u<<20));
}

// ---------------- bf16 mma.sync expert GEMM (pipelined) --------------------
// CTA: 128 pixels x 128 couts, one expert. 8 warps in 2(M)x4(N).
// Double-buffered smem, cp.async for B, register prefetch for A.
__global__ __launch_bounds__(256, 2)
void k_mma() {
    const int e    = blockIdx.y;
    const int tile = blockIdx.x;
    const int n    = (e < 8) ? g_count[e] : P_;
    if (tile * 128 >= n) return;

    extern __shared__ uint32_t dsm[];
    uint32_t* sAp = dsm;          // 2 stages x 4096 u32 (hi 2048 | lo 2048 each)
    uint32_t* sBp = dsm + 8192;   // 2 stages x 4096 u32
    __shared__ int   s_pid[128];
    __shared__ int   s_pp[128];
    __shared__ float s_wt[128];
    __shared__ float s_bias[128];

    const int tid = threadIdx.x;
    if (tid < 128) {
        int idx = tile*128 + tid;
        int pid = 0, slot = 0; float wt = 0.f;
        if (e < 8) {
            if (idx < n) {
                unsigned long long v = g_list[e][idx];
                wt   = __uint_as_float((unsigned)(v >> 32));
                unsigned lo = (unsigned)v;
                pid  = lo & 0xFFFFF;
                slot = (lo >> 20) & 1;
            }
        } else { pid = idx; wt = 1.f; slot = 2; }
        int b = pid / HW_, hw = pid - b*HW_;
        int h = hw / W_, w = hw - h*W_;
        s_pp[tid]   = (wt != 0.f) ? (b*HWP_ + (h+1)*WP_ + (w+1)) : (WP_ + 1);
        s_pid[tid]  = pid | (slot << 20);
        s_wt[tid]   = wt;
        s_bias[tid] = g_bias[e*C_ + tid];
    }
    __syncthreads();

    const int lane = tid & 31, wid = tid >> 5;
    const int wm = wid >> 2, wn = wid & 3;

    float c[4][4][4];
    #pragma unroll
    for (int i = 0; i < 4; i++)
        #pragma unroll
        for (int j = 0; j < 4; j++)
            #pragma unroll
            for (int k = 0; k < 4; k++) c[i][j][k] = 0.f;

    const int m_row = tid >> 3;      // A gather: 8 threads per pixel row
    const int kq    = tid & 7;
    const uint32_t sB_byte = smem_u32(sBp);
    const uint32_t* __restrict__ wbase = g_wBf + (size_t)e*NCHUNK*4096;

    uint4 pf[4];
    // ---- prologue: A chunk0 -> regs, B chunk0 -> sB stage0 via cp.async ----
    {
        const int off = -WP_ - 1;    // tap 0
        #pragma unroll
        for (int j = 0; j < 4; j++) {
            int m = m_row + j*32;
            pf[j] = *(const uint4*)(g_xT + (size_t)(s_pp[m] + off)*C_ + kq*4);
        }
        const uint4* bs = (const uint4*)wbase;
        #pragma unroll
        for (int j = 0; j < 4; j++)
            cp_async16(sB_byte + (tid + j*256)*16, bs + tid + j*256);
        CP_COMMIT();
    }

    for (int ch = 0; ch < NCHUNK; ch++) {
        const int st = ch & 1;
        uint32_t* sA = sAp + st*4096;
        uint32_t* sB = sBp + st*4096;

        // ---- STS A fragments from prefetched regs ----
        {
            const int k0 = kq * 4;
            const int ks = k0 >> 4;
            const int la = ((k0 & 7) >> 1);
            const int rg_k = ((k0 >> 3) & 1) << 1;
            #pragma unroll
            for (int j = 0; j < 4; j++) {
                int m = m_row + j*32;
                int mt = m >> 4;
                int lane_a = ((m & 7) << 2) + la;
                int rg = ((m >> 3) & 1) + rg_k;
                int bi = ((ks*8 + mt)*32 + lane_a)*4 + rg;
                uint4 v = pf[j];
                sA[bi]          = __byte_perm(v.x, v.y, 0x5410);
                sA[bi + 2048]   = __byte_perm(v.x, v.y, 0x7632);
                sA[bi + 4]      = __byte_perm(v.z, v.w, 0x5410);
                sA[bi + 4+2048] = __byte_perm(v.z, v.w, 0x7632);
            }
        }
        CP_WAIT0();          // B(ch) landed
        __syncthreads();     // sA[st] + sB[st] visible to all

        // ---- prefetch next chunk (overlaps mma below) ----
        if (ch + 1 < NCHUNK) {
            const int t = (ch+1) >> 2, ci0 = ((ch+1) & 3) * 32;
            const int off = (t/3 - 1)*WP_ + (t%3 - 1);
            #pragma unroll
            for (int j = 0; j < 4; j++) {
                int m = m_row + j*32;
                pf[j] = *(const uint4*)(g_xT + (size_t)(s_pp[m] + off)*C_ + ci0 + kq*4);
            }
            const uint4* bs = (const uint4*)(wbase + (size_t)(ch+1)*4096);
            const uint32_t dstb = sB_byte + (st^1)*16384;
            #pragma unroll
            for (int j = 0; j < 4; j++)
                cp_async16(dstb + (tid + j*256)*16, bs + tid + j*256);
            CP_COMMIT();
        }

        // ---- mma: 3-pass split bf16 ----
        #pragma unroll
        for (int ks = 0; ks < 2; ks++) {
            uint32_t bh[4][2], bl[4][2];
            #pragma unroll
            for (int nt = 0; nt < 4; nt++) {
                int ng = wn*4 + nt;
                uint2 h2 = ((const uint2*)(sB + (ks*16 + ng)*64))[lane];
                uint2 l2 = ((const uint2*)(sB + 2048 + (ks*16 + ng)*64))[lane];
                bh[nt][0] = h2.x; bh[nt][1] = h2.y;
                bl[nt][0] = l2.x; bl[nt][1] = l2.y;
            }
            #pragma unroll
            for (int mt = 0; mt < 4; mt++) {
                int mg = wm*4 + mt;
                uint4 ah4 = ((const uint4*)(sA + (ks*8 + mg)*128))[lane];
                uint4 al4 = ((const uint4*)(sA + 2048 + (ks*8 + mg)*128))[lane];
                uint32_t ah[4] = {ah4.x, ah4.y, ah4.z, ah4.w};
                uint32_t al[4] = {al4.x, al4.y, al4.z, al4.w};
                #pragma unroll
                for (int nt = 0; nt < 4; nt++) {
                    mma_bf16(c[mt][nt], ah, bh[nt]);
                    mma_bf16(c[mt][nt], ah, bl[nt]);
                    mma_bf16(c[mt][nt], al, bh[nt]);
                }
            }
        }
        // no trailing sync: next iter writes the OTHER stage; the single
        // barrier above separates stage-reuse by two iterations.
    }

    // ---- epilogue: (acc + bias) * wt  ->  g_partial[slot][pid][co] ----
    #pragma unroll
    for (int mt = 0; mt < 4; mt++) {
        int r0 = wm*64 + mt*16 + (lane >> 2);
        #pragma unroll
        for (int half = 0; half < 2; half++) {
            int r = r0 + half*8;
            float wt = s_wt[r];
            if (wt != 0.f) {
                int pm  = s_pid[r];
                int pid = pm & 0xFFFFF;
                int slot = pm >> 20;
                float* dst = g_partial + ((size_t)slot*P_ + pid)*C_;
                #pragma unroll
                for (int nt = 0; nt < 4; nt++) {
                    int n0 = (wn*4 + nt)*8 + (lane & 3)*2;
                    float2 v;
                    v.x = (c[mt][nt][half*2 + 0] + s_bias[n0])     * wt;
                    v.y = (c[mt][nt][half*2 + 1] + s_bias[n0 + 1]) * wt;
                    *(float2*)(dst + n0) = v;
                }
            }
        }
    }
}

// ---------------- combine: out = p0 + p1 + p2 (transpose to NCHW) ---------
__global__ void k_combine(float* __restrict__ out) {
    __shared__ float t[32][33];
    int pid0 = blockIdx.x * 32, co0 = blockIdx.y * 32;
    int tid = threadIdx.x;
    #pragma unroll
    for (int r = 0; r < 4; r++) {
        int i = r*256 + tid;
        int pr = i >> 5, cl = i & 31;
        size_t o0 = ((size_t)(pid0 + pr))*C_ + co0 + cl;
        t[cl][pr] = g_partial[o0] + g_partial[(size_t)P_*C_ + o0]
                  + g_partial[2*(size_t)P_*C_ + o0];
    }
    __syncthreads();
    #pragma unroll
    for (int r = 0; r < 4; r++) {
        int i = r*256 + tid;
        int cl = i >> 5, pl = i & 31;
        int pid = pid0 + pl;
        int b = pid / HW_, hw = pid - b*HW_;
        out[((size_t)b*C_ + co0 + cl)*HW_ + hw] = t[cl][pl];
    }
}

// ---------------- launch ---------------------------------------------------
extern "C" void kernel_launch(void* const* d_in, const int* in_sizes, int n_in,
                              void* d_out, int out_size) {
    const float* x  = (const float*)d_in[0];
    const float* gw = (const float*)d_in[1];
    const float* gb = (const float*)d_in[2];
    const float* ew = (const float*)d_in[3];
    const float* eb = (const float*)d_in[4];
    const float* sw = (const float*)d_in[5];
    const float* sb = (const float*)d_in[6];
    float* out = (float*)d_out;

    cudaFuncSetAttribute(k_mma, cudaFuncAttributeMaxDynamicSharedMemorySize, 65536);

    k_init<<<1, 32>>>();
    k_zero_xpad<<<(PPAD_*C_/4 + 255)/256, 256>>>();
    k_nhwc<<<dim3(HW_/32, C_/32, B_), 256>>>(x);
    k_repackB<<<(NEX*C_*9*64 + 255)/256, 256>>>(ew, sw, eb, sb);
    k_gate<<<(P_ + 255)/256, 256>>>(x, gw, gb);
    k_mma<<<dim3(P_/128, NEX), 256, 65536>>>();
    k_combine<<<dim3(P_/32, C_/32), 256>>>(out);
}

// round 6
// speedup vs baseline: 4.0708x; 1.6196x over previous
#include <cuda_runtime.h>
#include <cuda_bf16.h>
#include <cuda_fp16.h>
#include <cstdint>

#define B_    4
#define C_    128
#define H_    96
#define W_    96
#define HW_   (H_*W_)          // 9216
#define P_    (B_*HW_)         // 36864
#define E_    8
#define NEX   9
#define WP_   98
#define HP_   98
#define HWP_  (HP_*WP_)        // 9604
#define PPAD_ (B_*HWP_)        // 38416
#define NCHUNK 36              // K=1152 in chunks of 32

// ---------------- device globals (no allocation) --------------------------
__device__ __half   g_xh[PPAD_*C_];            // fp16 NHWC padded activations (9.8MB)
__device__ uint32_t g_wBf[NEX*NCHUNK*2048];    // fp16 B frags: [e][chunk]     (2.6MB)
__device__ float    g_bias[NEX*C_];
__device__ int      g_count[E_];
__device__ unsigned long long g_list[E_][P_];  // (w_bits<<32)|(slot<<20)|pid
__device__ float    g_partial[3*P_*C_];        // [slot][pid][co]  (56.6MB)

// ---------------- helpers --------------------------------------------------
__device__ __forceinline__ void mma_fp16(float* c, const uint32_t* a, const uint32_t* b) {
    asm volatile(
        "mma.sync.aligned.m16n8k16.row.col.f32.f16.f16.f32 "
        "{%0,%1,%2,%3}, {%4,%5,%6,%7}, {%8,%9}, {%0,%1,%2,%3};"
        : "+f"(c[0]), "+f"(c[1]), "+f"(c[2]), "+f"(c[3])
        : "r"(a[0]), "r"(a[1]), "r"(a[2]), "r"(a[3]), "r"(b[0]), "r"(b[1]));
}

__device__ __forceinline__ uint32_t smem_u32(const void* p) {
    uint32_t a;
    asm("{ .reg .u64 t; cvta.to.shared.u64 t, %1; cvt.u32.u64 %0, t; }" : "=r"(a) : "l"(p));
    return a;
}
__device__ __forceinline__ void cp_async16(uint32_t dst, const void* src) {
    asm volatile("cp.async.cg.shared.global [%0], [%1], 16;" :: "r"(dst), "l"(src) : "memory");
}
#define CP_COMMIT() asm volatile("cp.async.commit_group;" ::: "memory")
#define CP_WAIT0()  asm volatile("cp.async.wait_group 0;" ::: "memory")

// ---------------- prep kernels ---------------------------------------------
__global__ void k_init() {
    int i = blockIdx.x * blockDim.x + threadIdx.x;
    if (i < E_) g_count[i] = 0;
}

__global__ void k_zero_xpad() {
    int i = blockIdx.x * blockDim.x + threadIdx.x;
    if (i < PPAD_*C_/8) ((uint4*)g_xh)[i] = make_uint4(0u, 0u, 0u, 0u);
}

__global__ void k_nhwc(const float* __restrict__ x) {
    __shared__ float t[32][33];
    int hw0 = blockIdx.x * 32, ci0 = blockIdx.y * 32, b = blockIdx.z;
    int tid = threadIdx.x;
    #pragma unroll
    for (int r = 0; r < 4; r++) {
        int ci = (tid >> 5) + r*8, hw = tid & 31;
        t[ci][hw] = x[((b*C_) + ci0 + ci)*HW_ + hw0 + hw];
    }
    __syncthreads();
    #pragma unroll
    for (int r = 0; r < 4; r++) {
        int hwl = (tid >> 5) + r*8, cil = tid & 31;
        int hw = hw0 + hwl, h = hw / W_, w = hw - h*W_;
        int pad = b*HWP_ + (h+1)*WP_ + (w+1);
        g_xh[(size_t)pad*C_ + ci0 + cil] = __float2half_rn(t[cil][hwl]);
    }
}

// weights -> fp16 mma fragment order, packed per ci pair
__global__ void k_repackB(const float* __restrict__ ew, const float* __restrict__ sw,
                          const float* __restrict__ eb, const float* __restrict__ sb) {
    int idx = blockIdx.x * blockDim.x + threadIdx.x;
    const int total = NEX*C_*9*64;
    if (idx < total) {
        int cip = idx & 63;
        int tap = (idx >> 6) % 9;
        int co  = (idx / (64*9)) & 127;
        int e   = idx / (64*9*C_);
        int ci  = cip * 2;
        float v0, v1;
        if (e < 8) {
            int base = ((e*C_ + co)*C_ + ci)*9 + tap;
            v0 = ew[base]; v1 = ew[base + 9];
        } else {
            int base = (co*C_ + ci)*9 + tap;
            v0 = sw[base]; v1 = sw[base + 9];
        }
        uint32_t h0 = (uint32_t)__half_as_ushort(__float2half_rn(v0));
        uint32_t h1 = (uint32_t)__half_as_ushort(__float2half_rn(v1));
        int k_abs = tap*C_ + ci;
        int chunk = k_abs >> 5;
        int k0 = k_abs & 31;
        int ks = k0 >> 4;
        int lane = ((co & 7) << 2) + ((k0 & 7) >> 1);
        int reg  = (k0 >> 3) & 1;
        int nt   = co >> 3;
        size_t di = (size_t)(e*NCHUNK + chunk)*2048 + ((ks*16 + nt)*32 + lane)*2 + reg;
        g_wBf[di] = h0 | (h1 << 16);
    }
    if (idx < NEX*C_) {
        int ex = idx >> 7, co = idx & 127;
        g_bias[idx] = (ex < 8) ? eb[idx] : sb[co];
    }
}

// ---------------- gate: conv(8) + sigmoid + top2 + softmax + route --------
__global__ void k_gate(const float* __restrict__ x, const float* __restrict__ gw,
                       const float* __restrict__ gbias) {
    __shared__ float sgw[E_*C_*9];
    for (int i = threadIdx.x; i < E_*C_*9; i += blockDim.x) sgw[i] = gw[i];
    __syncthreads();

    int pid = blockIdx.x * blockDim.x + threadIdx.x;
    if (pid >= P_) return;
    int b = pid / HW_, hw = pid - b*HW_;
    int h = hw / W_, w = hw - h*W_;
    const float* xb = x + (size_t)b*C_*HW_ + hw;
    bool hm = h > 0, hp = h < H_-1, wm = w > 0, wp = w < W_-1;

    float acc[E_];
    #pragma unroll
    for (int e = 0; e < E_; e++) acc[e] = 0.f;
    for (int ci = 0; ci < C_; ci++) {
        const float* xp = xb + ci*HW_;
        float xv[9];
        xv[0] = (hm && wm) ? xp[-W_-1] : 0.f;
        xv[1] =  hm        ? xp[-W_]   : 0.f;
        xv[2] = (hm && wp) ? xp[-W_+1] : 0.f;
        xv[3] =  wm        ? xp[-1]    : 0.f;
        xv[4] =              xp[0];
        xv[5] =  wp        ? xp[1]     : 0.f;
        xv[6] = (hp && wm) ? xp[W_-1]  : 0.f;
        xv[7] =  hp        ? xp[W_]    : 0.f;
        xv[8] = (hp && wp) ? xp[W_+1]  : 0.f;
        #pragma unroll
        for (int e = 0; e < E_; e++) {
            const float* wp9 = &sgw[(e*C_ + ci)*9];
            float a = acc[e];
            #pragma unroll
            for (int t = 0; t < 9; t++) a = fmaf(xv[t], wp9[t], a);
            acc[e] = a;
        }
    }
    float s[E_], bsc[E_];
    #pragma unroll
    for (int e = 0; e < E_; e++) {
        s[e]   = 1.f / (1.f + expf(-acc[e]));
        bsc[e] = s[e] + gbias[e];
    }
    int e0 = 0;
    #pragma unroll
    for (int e = 1; e < E_; e++) if (bsc[e] > bsc[e0]) e0 = e;
    int e1 = (e0 == 0) ? 1 : 0;
    #pragma unroll
    for (int e = 0; e < E_; e++) if (e != e0 && bsc[e] > bsc[e1]) e1 = e;
    float m = fmaxf(s[e0], s[e1]);
    float d0 = expf(s[e0]-m), d1 = expf(s[e1]-m);
    float inv = 1.f / (d0 + d1);
    int p0 = atomicAdd(&g_count[e0], 1);
    g_list[e0][p0] = (((unsigned long long)__float_as_uint(d0*inv)) << 32) | (unsigned)pid;
    int p1 = atomicAdd(&g_count[e1], 1);
    g_list[e1][p1] = (((unsigned long long)__float_as_uint(d1*inv)) << 32) | (unsigned)(pid | (1u<<20));
}

// ---------------- fp16 mma.sync expert GEMM (pipelined, single-pass) ------
// CTA: 128 pixels x 128 couts, one expert. 8 warps in 2(M)x4(N).
__global__ __launch_bounds__(256, 2)
void k_mma() {
    const int e    = blockIdx.y;
    const int tile = blockIdx.x;
    const int n    = (e < 8) ? g_count[e] : P_;
    if (tile * 128 >= n) return;

    extern __shared__ uint32_t dsm[];
    uint32_t* sAp = dsm;          // 2 stages x 2048 u32
    uint32_t* sBp = dsm + 4096;   // 2 stages x 2048 u32
    __shared__ int   s_pid[128];
    __shared__ int   s_pp[128];
    __shared__ float s_wt[128];
    __shared__ float s_bias[128];

    const int tid = threadIdx.x;
    if (tid < 128) {
        int idx = tile*128 + tid;
        int pid = 0, slot = 0; float wt = 0.f;
        if (e < 8) {
            if (idx < n) {
                unsigned long long v = g_list[e][idx];
                wt   = __uint_as_float((unsigned)(v >> 32));
                unsigned lo = (unsigned)v;
                pid  = lo & 0xFFFFF;
                slot = (lo >> 20) & 1;
            }
        } else { pid = idx; wt = 1.f; slot = 2; }
        int b = pid / HW_, hw = pid - b*HW_;
        int h = hw / W_, w = hw - h*W_;
        s_pp[tid]   = (wt != 0.f) ? (b*HWP_ + (h+1)*WP_ + (w+1)) : (WP_ + 1);
        s_pid[tid]  = pid | (slot << 20);
        s_wt[tid]   = wt;
        s_bias[tid] = g_bias[e*C_ + tid];
    }
    __syncthreads();

    const int lane = tid & 31, wid = tid >> 5;
    const int wm = wid >> 2, wn = wid & 3;

    float c[4][4][4];
    #pragma unroll
    for (int i = 0; i < 4; i++)
        #pragma unroll
        for (int j = 0; j < 4; j++)
            #pragma unroll
            for (int k = 0; k < 4; k++) c[i][j][k] = 0.f;

    const int m_row = tid >> 3;      // A gather: 8 threads per pixel row
    const int kq    = tid & 7;       // each covers 4 ci (8 bytes fp16)
    const uint32_t sB_byte = smem_u32(sBp);
    const uint32_t* __restrict__ wbase = g_wBf + (size_t)e*NCHUNK*2048;

    uint2 pf[4];
    // ---- prologue: A chunk0 -> regs, B chunk0 -> sB stage0 via cp.async ----
    {
        const int off = -WP_ - 1;    // tap 0
        #pragma unroll
        for (int j = 0; j < 4; j++) {
            int m = m_row + j*32;
            pf[j] = *(const uint2*)(g_xh + (size_t)(s_pp[m] + off)*C_ + kq*4);
        }
        const uint4* bs = (const uint4*)wbase;
        #pragma unroll
        for (int j = 0; j < 2; j++)
            cp_async16(sB_byte + (tid + j*256)*16, bs + tid + j*256);
        CP_COMMIT();
    }

    for (int ch = 0; ch < NCHUNK; ch++) {
        const int st = ch & 1;
        uint32_t* sA = sAp + st*2048;
        uint32_t* sB = sBp + st*2048;

        // ---- STS A fragments from prefetched regs (already frag-order u32) ----
        {
            const int k0 = kq * 4;
            const int ks = k0 >> 4;
            const int la = ((k0 & 7) >> 1);
            const int rg_k = ((k0 >> 3) & 1) << 1;
            #pragma unroll
            for (int j = 0; j < 4; j++) {
                int m = m_row + j*32;
                int mt = m >> 4;
                int lane_a = ((m & 7) << 2) + la;
                int rg = ((m >> 3) & 1) + rg_k;
                int bi = ((ks*8 + mt)*32 + lane_a)*4 + rg;
                sA[bi]     = pf[j].x;   // (ci0, ci1)
                sA[bi + 4] = pf[j].y;   // (ci2, ci3)
            }
        }
        CP_WAIT0();          // B(ch) landed
        __syncthreads();     // sA[st] + sB[st] visible to all

        // ---- prefetch next chunk (overlaps mma below) ----
        if (ch + 1 < NCHUNK) {
            const int t = (ch+1) >> 2, ci0 = ((ch+1) & 3) * 32;
            const int off = (t/3 - 1)*WP_ + (t%3 - 1);
            #pragma unroll
            for (int j = 0; j < 4; j++) {
                int m = m_row + j*32;
                pf[j] = *(const uint2*)(g_xh + (size_t)(s_pp[m] + off)*C_ + ci0 + kq*4);
            }
            const uint4* bs = (const uint4*)(wbase + (size_t)(ch+1)*2048);
            const uint32_t dstb = sB_byte + (st^1)*8192;
            #pragma unroll
            for (int j = 0; j < 2; j++)
                cp_async16(dstb + (tid + j*256)*16, bs + tid + j*256);
            CP_COMMIT();
        }

        // ---- mma: single-pass fp16 ----
        #pragma unroll
        for (int ks = 0; ks < 2; ks++) {
            uint32_t bh[4][2];
            #pragma unroll
            for (int nt = 0; nt < 4; nt++) {
                int ng = wn*4 + nt;
                uint2 h2 = ((const uint2*)(sB + (ks*16 + ng)*64))[lane];
                bh[nt][0] = h2.x; bh[nt][1] = h2.y;
            }
            #pragma unroll
            for (int mt = 0; mt < 4; mt++) {
                int mg = wm*4 + mt;
                uint4 ah4 = ((const uint4*)(sA + (ks*8 + mg)*128))[lane];
                uint32_t ah[4] = {ah4.x, ah4.y, ah4.z, ah4.w};
                #pragma unroll
                for (int nt = 0; nt < 4; nt++)
                    mma_fp16(c[mt][nt], ah, bh[nt]);
            }
        }
        // no trailing sync: 2-stage rotation, single barrier per chunk.
    }

    // ---- epilogue: (acc + bias) * wt  ->  g_partial[slot][pid][co] ----
    #pragma unroll
    for (int mt = 0; mt < 4; mt++) {
        int r0 = wm*64 + mt*16 + (lane >> 2);
        #pragma unroll
        for (int half = 0; half < 2; half++) {
            int r = r0 + half*8;
            float wt = s_wt[r];
            if (wt != 0.f) {
                int pm  = s_pid[r];
                int pid = pm & 0xFFFFF;
                int slot = pm >> 20;
                float* dst = g_partial + ((size_t)slot*P_ + pid)*C_;
                #pragma unroll
                for (int nt = 0; nt < 4; nt++) {
                    int n0 = (wn*4 + nt)*8 + (lane & 3)*2;
                    float2 v;
                    v.x = (c[mt][nt][half*2 + 0] + s_bias[n0])     * wt;
                    v.y = (c[mt][nt][half*2 + 1] + s_bias[n0 + 1]) * wt;
                    *(float2*)(dst + n0) = v;
                }
            }
        }
    }
}

// ---------------- combine: out = p0 + p1 + p2 (transpose to NCHW) ---------
__global__ void k_combine(float* __restrict__ out) {
    __shared__ float t[32][33];
    int pid0 = blockIdx.x * 32, co0 = blockIdx.y * 32;
    int tid = threadIdx.x;
    #pragma unroll
    for (int r = 0; r < 4; r++) {
        int i = r*256 + tid;
        int pr = i >> 5, cl = i & 31;
        size_t o0 = ((size_t)(pid0 + pr))*C_ + co0 + cl;
        t[cl][pr] = g_partial[o0] + g_partial[(size_t)P_*C_ + o0]
                  + g_partial[2*(size_t)P_*C_ + o0];
    }
    __syncthreads();
    #pragma unroll
    for (int r = 0; r < 4; r++) {
        int i = r*256 + tid;
        int cl = i >> 5, pl = i & 31;
        int pid = pid0 + pl;
        int b = pid / HW_, hw = pid - b*HW_;
        out[((size_t)b*C_ + co0 + cl)*HW_ + hw] = t[cl][pl];
    }
}

// ---------------- launch ---------------------------------------------------
extern "C" void kernel_launch(void* const* d_in, const int* in_sizes, int n_in,
                              void* d_out, int out_size) {
    const float* x  = (const float*)d_in[0];
    const float* gw = (const float*)d_in[1];
    const float* gb = (const float*)d_in[2];
    const float* ew = (const float*)d_in[3];
    const float* eb = (const float*)d_in[4];
    const float* sw = (const float*)d_in[5];
    const float* sb = (const float*)d_in[6];
    float* out = (float*)d_out;

    cudaFuncSetAttribute(k_mma, cudaFuncAttributeMaxDynamicSharedMemorySize, 32768);

    k_init<<<1, 32>>>();
    k_zero_xpad<<<(PPAD_*C_/8 + 255)/256, 256>>>();
    k_nhwc<<<dim3(HW_/32, C_/32, B_), 256>>>(x);
    k_repackB<<<(NEX*C_*9*64 + 255)/256, 256>>>(ew, sw, eb, sb);
    k_gate<<<(P_ + 255)/256, 256>>>(x, gw, gb);
    k_mma<<<dim3(P_/128, NEX), 256, 32768>>>();
    k_combine<<<dim3(P_/32, C_/32), 256>>>(out);
}